// round 9
// baseline (speedup 1.0000x reference)
#include <cuda_runtime.h>
#include <stdint.h>
#include <math.h>

// ---------------- problem dims ----------------------------------------------
#define NB   4
#define NL   2048
#define ND   1024
#define NH   4096
#define NV   32000
#define NEXP 16
#define NTOK (NB*NL)     // 8192
#define KCAT (2*NH)      // 8192

// ---------------- persistent scratch (no allocation allowed) -----------------
__device__ __align__(256) int8_t g_Xq1[NTOK * ND];
__device__ __align__(256) int8_t g_Xq2[NTOK * ND];
__device__ float  g_Xs[NTOK];
__device__ float  g_Hbuf[(size_t)NTOK * KCAT];          // 268 MB fp32
__device__ __align__(256) int8_t g_Hq1[(size_t)NTOK * KCAT];
__device__ __align__(256) int8_t g_Hq2[(size_t)NTOK * KCAT];
__device__ float  g_Hs[NTOK];
__device__ float  g_Obuf[NTOK * ND];
__device__ __align__(256) int8_t g_Oq1[NTOK * ND];
__device__ __align__(256) int8_t g_Oq2[NTOK * ND];
__device__ float  g_Os[NTOK];
__device__ __align__(256) int8_t g_w1q1[(size_t)2 * NH * ND];
__device__ __align__(256) int8_t g_w1q2[(size_t)2 * NH * ND];
__device__ float  g_w1s[2 * NH];
__device__ __align__(256) int8_t g_w2q1[(size_t)ND * KCAT];
__device__ __align__(256) int8_t g_w2q2[(size_t)ND * KCAT];
__device__ float  g_w2s[ND];
__device__ __align__(256) int8_t g_whq1[(size_t)NV * ND];
__device__ __align__(256) int8_t g_whq2[(size_t)NV * ND];
__device__ float  g_whs[NV];
__device__ float g_pool_part[64 * ND];
__device__ float g_pool[ND];
__device__ int   g_eidx[2];
__device__ float g_ewt[2];

// ---------------- helpers -----------------------------------------------------
__device__ __forceinline__ float gelu_tanh(float x) {
    const float u = 0.7978845608028654f * (x + 0.044715f * x * x * x);
    return 0.5f * x * (1.0f + tanhf(u));
}
__device__ __forceinline__ uint32_t s2u(const void* p) {
    uint32_t a;
    asm("{ .reg .u64 t; cvta.to.shared.u64 t, %1; cvt.u32.u64 %0, t; }"
        : "=r"(a) : "l"(p));
    return a;
}
// two-digit int8 quantization: a ~= (s/127)*(q1 + q2/254)
__device__ __forceinline__ void q8(float a, float inv, int8_t& q1, int8_t& q2) {
    const float x = a * inv;          // in [-127, 127]
    const float r = rintf(x);
    q1 = (int8_t)(int)r;
    q2 = (int8_t)(int)rintf((x - r) * 254.f);
}

__device__ __forceinline__ void mma_s8(int* d, const uint32_t* a,
                                       const uint32_t* b) {
    asm volatile(
        "mma.sync.aligned.m16n8k32.row.col.s32.s8.s8.s32 "
        "{%0,%1,%2,%3}, {%4,%5,%6,%7}, {%8,%9}, {%0,%1,%2,%3};"
        : "+r"(d[0]), "+r"(d[1]), "+r"(d[2]), "+r"(d[3])
        : "r"(a[0]), "r"(a[1]), "r"(a[2]), "r"(a[3]),
          "r"(b[0]), "r"(b[1]));
}

#define LDSM4(r0, r1, r2, r3, addr) \
    asm volatile("ldmatrix.sync.aligned.m8n8.x4.shared.b16 {%0,%1,%2,%3}, [%4];" \
        : "=r"(r0), "=r"(r1), "=r"(r2), "=r"(r3) : "r"(addr))

#define CPASYNC16(dst, src) \
    asm volatile("cp.async.cg.shared.global [%0], [%1], 16;" \
        :: "r"(dst), "l"(src) : "memory")
#define CPCOMMIT() asm volatile("cp.async.commit_group;" ::: "memory")
#define CPWAIT2()  asm volatile("cp.async.wait_group 2;"  ::: "memory")

#define SWZ16(ci) ((uint32_t)(((ci) ^ (((ci) >> 3) & 1)) * 16))

// ---------------- embed gather + quantize ------------------------------------
__global__ void gather_quant_kernel(const int* __restrict__ ids,
                                    const float* __restrict__ emb)
{
    __shared__ float red[256];
    const int t = blockIdx.x;
    const int id = ids[t];
    const int tid = threadIdx.x;
    const int c = tid * 4;
    const float4 v = *(const float4*)(emb + (size_t)id * ND + c);
    float m = fmaxf(fmaxf(fabsf(v.x), fabsf(v.y)), fmaxf(fabsf(v.z), fabsf(v.w)));
    red[tid] = m;
    __syncthreads();
    for (int s = 128; s > 0; s >>= 1) {
        if (tid < s) red[tid] = fmaxf(red[tid], red[tid + s]);
        __syncthreads();
    }
    const float sc = fmaxf(red[0], 1e-30f);
    const float inv = 127.f / sc;
    int8_t a1, a2, b1, b2, c1, c2, d1, d2;
    q8(v.x, inv, a1, a2); q8(v.y, inv, b1, b2);
    q8(v.z, inv, c1, c2); q8(v.w, inv, d1, d2);
    *(char4*)(g_Xq1 + (size_t)t * ND + c) = make_char4(a1, b1, c1, d1);
    *(char4*)(g_Xq2 + (size_t)t * ND + c) = make_char4(a2, b2, c2, d2);
    if (tid == 0) g_Xs[t] = sc;
}

// ---------------- pool / router -------------------------------------------------
__global__ void pool_partial_kernel(const int* __restrict__ ids,
                                    const float* __restrict__ emb)
{
    __shared__ int sid[128];
    const int t0 = blockIdx.x * 128;
    if (threadIdx.x < 128) sid[threadIdx.x] = ids[t0 + threadIdx.x];
    __syncthreads();
    const int c = threadIdx.x * 4;
    float4 s = make_float4(0.f, 0.f, 0.f, 0.f);
    for (int t = 0; t < 128; ++t) {
        const float4 v = *(const float4*)(emb + (size_t)sid[t] * ND + c);
        s.x += v.x; s.y += v.y; s.z += v.z; s.w += v.w;
    }
    *(float4*)(g_pool_part + blockIdx.x * ND + c) = s;
}

__global__ void pool_final_kernel()
{
    const int c = threadIdx.x * 4;
    float4 s = make_float4(0.f, 0.f, 0.f, 0.f);
    for (int b = 0; b < 64; ++b) {
        const float4 v = *(const float4*)(g_pool_part + b * ND + c);
        s.x += v.x; s.y += v.y; s.z += v.z; s.w += v.w;
    }
    const float inv = 1.0f / (float)NTOK;
    s.x *= inv; s.y *= inv; s.z *= inv; s.w *= inv;
    *(float4*)(g_pool + c) = s;
}

__global__ void router_kernel(const float* __restrict__ w_router)
{
    __shared__ float slog[NEXP];
    const int warp = threadIdx.x >> 5;
    const int lane = threadIdx.x & 31;
    float s = 0.f;
    for (int d = lane; d < ND; d += 32)
        s += g_pool[d] * w_router[d * NEXP + warp];
    #pragma unroll
    for (int o = 16; o > 0; o >>= 1) s += __shfl_down_sync(0xffffffffu, s, o);
    if (lane == 0) slog[warp] = s;
    __syncthreads();
    if (threadIdx.x == 0) {
        float v0 = -1e30f, v1 = -1e30f; int i0 = 0, i1 = 0;
        for (int n = 0; n < NEXP; ++n) {
            const float l = slog[n];
            if (l > v0) { v1 = v0; i1 = i0; v0 = l; i0 = n; }
            else if (l > v1) { v1 = l; i1 = n; }
        }
        const float e1  = expf(v1 - v0);
        const float den = 1.0f + e1;
        g_eidx[0] = i0; g_eidx[1] = i1;
        g_ewt[0] = 1.0f / den; g_ewt[1] = e1 / den;
    }
}

// ---------------- weight scale (column max) -----------------------------------
__global__ void zero_ws_kernel()
{
    const int i = blockIdx.x * 256 + threadIdx.x;
    if (i < 2 * NH) g_w1s[i] = 0.f;
    if (i < ND)     g_w2s[i] = 0.f;
}

__global__ void colmax_w1_kernel(const float* __restrict__ w1)
{   // grid (NH/256, 2, ND/128)
    const int e  = blockIdx.y;
    const int ex = g_eidx[e];
    const int h  = blockIdx.x * 256 + threadIdx.x;
    const int d0 = blockIdx.z * 128;
    float m = 0.f;
    for (int d = d0; d < d0 + 128; ++d)
        m = fmaxf(m, fabsf(w1[(size_t)ex * ND * NH + (size_t)d * NH + h]));
    atomicMax((unsigned*)&g_w1s[e * NH + h], __float_as_uint(m));
}

__global__ void colmax_w2_kernel(const float* __restrict__ w2)
{   // grid (ND/256, 2, NH/128)
    const int e  = blockIdx.y;
    const int ex = g_eidx[e];
    const int d  = blockIdx.x * 256 + threadIdx.x;
    const int h0 = blockIdx.z * 128;
    float m = 0.f;
    for (int h = h0; h < h0 + 128; ++h)
        m = fmaxf(m, fabsf(w2[(size_t)ex * NH * ND + (size_t)h * ND + d]));
    atomicMax((unsigned*)&g_w2s[d], __float_as_uint(m));
}

__global__ void colmax_wh_kernel(const float* __restrict__ wh)
{   // grid (NV/256)
    const int v = blockIdx.x * 256 + threadIdx.x;
    float m = 0.f;
    for (int d = 0; d < ND; ++d)
        m = fmaxf(m, fabsf(wh[(size_t)d * NV + v]));
    g_whs[v] = m;
}

// ---------------- weight transpose + quantize ----------------------------------
__global__ void transpose_quant_kernel(const float* __restrict__ src,
                                       int K, int N, long src_z, int mode)
{
    __shared__ float tile[32][33];
    const int e = blockIdx.z;
    int8_t *dq1, *dq2; const float* sc; long dst_z; int ld; int use_e; int sc_off;
    if (mode == 0)      { dq1 = g_w1q1; dq2 = g_w1q2; sc = g_w1s; dst_z = (long)NH * ND; ld = ND;   use_e = 1; sc_off = e * NH; }
    else if (mode == 1) { dq1 = g_w2q1; dq2 = g_w2q2; sc = g_w2s; dst_z = NH;            ld = KCAT; use_e = 1; sc_off = 0; }
    else                { dq1 = g_whq1; dq2 = g_whq2; sc = g_whs; dst_z = 0;             ld = ND;   use_e = 0; sc_off = 0; }

    const int sel = use_e ? g_eidx[e] : e;
    const float* in = src + (size_t)sel * src_z;
    dq1 += (size_t)e * dst_z;
    dq2 += (size_t)e * dst_z;

    const int n0 = blockIdx.x * 32, k0 = blockIdx.y * 32;
    const int tx = threadIdx.x, ty = threadIdx.y;   // (32, 8)
    #pragma unroll
    for (int j = 0; j < 32; j += 8)
        tile[ty + j][tx] = in[(size_t)(k0 + ty + j) * N + n0 + tx];
    __syncthreads();
    #pragma unroll
    for (int j = 0; j < 32; j += 8) {
        const int row = n0 + ty + j;
        const float s = fmaxf(sc[sc_off + row], 1e-30f);
        const float inv = 127.f / s;
        int8_t q1v, q2v;
        q8(tile[tx][ty + j], inv, q1v, q2v);
        const size_t o = (size_t)row * ld + k0 + tx;
        dq1[o] = q1v; dq2[o] = q2v;
    }
}

// ---------------- row quantize for intermediates --------------------------------
// WHICH 0: g_Hbuf (W=KCAT) -> g_Hq1/g_Hq2/g_Hs
// WHICH 1: g_Obuf (W=ND)   -> g_Oq1/g_Oq2/g_Os
// Globals referenced INSIDE device code (host must not pass __device__ symbols).
template<int WHICH>
__global__ void quant_rows_kernel()
{
    constexpr int W = (WHICH == 0) ? KCAT : ND;
    const float* src = (WHICH == 0) ? g_Hbuf : g_Obuf;
    int8_t* q1 = (WHICH == 0) ? g_Hq1 : g_Oq1;
    int8_t* q2 = (WHICH == 0) ? g_Hq2 : g_Oq2;
    float*  sc = (WHICH == 0) ? g_Hs  : g_Os;

    __shared__ float red[256];
    const int row = blockIdx.x;
    const int tid = threadIdx.x;
    const float* p = src + (size_t)row * W;
    float m = 0.f;
    #pragma unroll
    for (int i = tid * 4; i < W; i += 1024) {
        const float4 v = *(const float4*)(p + i);
        m = fmaxf(m, fmaxf(fmaxf(fabsf(v.x), fabsf(v.y)),
                           fmaxf(fabsf(v.z), fabsf(v.w))));
    }
    red[tid] = m;
    __syncthreads();
    for (int s = 128; s > 0; s >>= 1) {
        if (tid < s) red[tid] = fmaxf(red[tid], red[tid + s]);
        __syncthreads();
    }
    const float s = fmaxf(red[0], 1e-30f);
    const float inv = 127.f / s;
    #pragma unroll
    for (int i = tid * 4; i < W; i += 1024) {
        const float4 v = *(const float4*)(p + i);
        int8_t a1, a2, b1, b2, c1, c2, d1, d2;
        q8(v.x, inv, a1, a2); q8(v.y, inv, b1, b2);
        q8(v.z, inv, c1, c2); q8(v.w, inv, d1, d2);
        *(char4*)(q1 + (size_t)row * W + i) = make_char4(a1, b1, c1, d1);
        *(char4*)(q2 + (size_t)row * W + i) = make_char4(a2, b2, c2, d2);
    }
    if (tid == 0) sc[row] = s;
}

// ---------------- int8 two-digit mma GEMM, 4-stage, 2 CTAs/SM -------------------
#define BM 128
#define BN 64
#define BK 32
#define NSTAGE 4
// per-stage: Aq1[128x32B] Aq2[128x32B] Bq1[64x32B] Bq2[64x32B]
#define OFF_A2 4096
#define OFF_B1 8192
#define OFF_B2 10240
#define STAGE  12288
#define SMEM_BYTES (NSTAGE * STAGE)   // 49152

// MODE 0: Hbuf = gelu((X @ w1t[e]^T))*wt[e]   fp32   (grid.z = expert)
// MODE 1: Obuf = H @ w2t^T                    fp32
// MODE 2: LOGITS = O @ wht^T                  fp32 out
template<int MODE>
__global__ void __launch_bounds__(256, 2)
mma_gemm_kernel(float* __restrict__ Cext)
{
    constexpr int K   = (MODE == 1) ? KCAT : ND;
    constexpr int NT  = K / BK;
    constexpr int LDC = (MODE == 0) ? KCAT : ((MODE == 1) ? ND : NV);

    const int8_t *Aq1, *Aq2, *Bq1, *Bq2;
    const float *Asc, *Bsc;
    if (MODE == 0)      { Aq1 = g_Xq1; Aq2 = g_Xq2; Asc = g_Xs;
                          Bq1 = g_w1q1; Bq2 = g_w1q2; Bsc = g_w1s; }
    else if (MODE == 1) { Aq1 = g_Hq1; Aq2 = g_Hq2; Asc = g_Hs;
                          Bq1 = g_w2q1; Bq2 = g_w2q2; Bsc = g_w2s; }
    else                { Aq1 = g_Oq1; Aq2 = g_Oq2; Asc = g_Os;
                          Bq1 = g_whq1; Bq2 = g_whq2; Bsc = g_whs; }
    float* C = (MODE == 0) ? g_Hbuf : ((MODE == 1) ? g_Obuf : Cext);

    extern __shared__ __align__(16) uint8_t smraw[];
    const uint32_t smb = s2u(smraw);

    const int tid  = threadIdx.x;
    const int w    = tid >> 5, lane = tid & 31;
    const int g    = lane >> 2, tig = lane & 3;
    const int mb   = (w >> 2) * 64;        // 2 m-warps
    const int nb   = (w & 3) * 16;         // 4 n-warps x 16
    const int bm   = blockIdx.y * BM;
    const int bn   = blockIdx.x * BN;

    float wt = 1.f; int ccol0 = bn;
    if (MODE == 0) {
        const int e = blockIdx.z;
        wt    = g_ewt[e];
        Bq1  += (size_t)e * NH * ND;
        Bq2  += (size_t)e * NH * ND;
        ccol0 = e * NH + bn;
    }

    const int8_t* Ab1 = Aq1 + (size_t)bm * K;
    const int8_t* Ab2 = Aq2 + (size_t)bm * K;
    const int8_t* Bb1 = Bq1 + (size_t)bn * K;
    const int8_t* Bb2 = Bq2 + (size_t)bn * K;

    // fill: A 256 chunks x2 digits (all threads), B 128 chunks x2 (half threads each)
    const int cib = tid & 127;
    const int8_t* bfsrc = (tid < 128) ? Bb1 : Bb2;
    const uint32_t bfoff = (tid < 128) ? OFF_B1 : OFF_B2;
    auto fill = [&](uint32_t sbase, int k0) {
        const size_t goA = (size_t)(tid >> 1) * K + k0 + (tid & 1) * 16;
        CPASYNC16(sbase + SWZ16(tid),          Ab1 + goA);
        CPASYNC16(sbase + OFF_A2 + SWZ16(tid), Ab2 + goA);
        const size_t goB = (size_t)(cib >> 1) * K + k0 + (cib & 1) * 16;
        CPASYNC16(sbase + bfoff + SWZ16(cib),  bfsrc + goB);
    };

    // ldmatrix lane offsets (byte layout identical to round-6 bf16 version)
    const int am = lane >> 3;
    const int a_ci0 = (mb + ((am & 1) << 3) + (lane & 7)) * 2 + (am >> 1);
    const uint32_t aoff = SWZ16(a_ci0);
    const int bmm = lane >> 3;
    const int b_ci0 = (nb + ((bmm >> 1) << 3) + (lane & 7)) * 2 + (bmm & 1);
    const uint32_t boff = SWZ16(b_ci0);

    int acc1[4][2][4], acc2[4][2][4];
    #pragma unroll
    for (int i = 0; i < 4; ++i)
        #pragma unroll
        for (int j = 0; j < 2; ++j)
            #pragma unroll
            for (int q = 0; q < 4; ++q) { acc1[i][j][q] = 0; acc2[i][j][q] = 0; }

    fill(smb, 0);                  CPCOMMIT();
    fill(smb + STAGE, BK);         CPCOMMIT();
    fill(smb + 2 * STAGE, 2 * BK); CPCOMMIT();

    int rd = 0, wr = 3;
    #pragma unroll 1
    for (int t = 0; t < NT; ++t) {
        CPWAIT2();
        __syncthreads();

        const uint32_t sb = smb + rd * STAGE;

        // B fragments: nt0 = {r0,r1}, nt1 = {r2,r3}
        uint32_t B1f[2][2], B2f[2][2];
        {
            uint32_t r0, r1, r2, r3;
            LDSM4(r0, r1, r2, r3, sb + OFF_B1 + boff);
            B1f[0][0] = r0; B1f[0][1] = r1; B1f[1][0] = r2; B1f[1][1] = r3;
            LDSM4(r0, r1, r2, r3, sb + OFF_B2 + boff);
            B2f[0][0] = r0; B2f[0][1] = r1; B2f[1][0] = r2; B2f[1][1] = r3;
        }

        if (t + 3 < NT) fill(smb + wr * STAGE, (t + 3) * BK);
        CPCOMMIT();

        #pragma unroll
        for (int mt = 0; mt < 4; ++mt) {
            uint32_t A1f[4], A2f[4];
            LDSM4(A1f[0], A1f[1], A1f[2], A1f[3], sb + aoff + mt * 512);
            LDSM4(A2f[0], A2f[1], A2f[2], A2f[3], sb + OFF_A2 + aoff + mt * 512);
            #pragma unroll
            for (int nt = 0; nt < 2; ++nt) {
                mma_s8(acc1[mt][nt], A1f, B1f[nt]);   // S1 = q1*q1
                mma_s8(acc2[mt][nt], A1f, B2f[nt]);   // S2 += q1*q2
                mma_s8(acc2[mt][nt], A2f, B1f[nt]);   // S2 += q2*q1
            }
        }

        rd = (rd + 1) & 3;
        wr = (wr + 1) & 3;
    }

    // ---- epilogue: C = sA*sB/127^2 * (S1 + S2/254) ----
    const float INV254   = 1.f / 254.f;
    const float INV127SQ = 1.f / 16129.f;
    float tb[2][2];
    #pragma unroll
    for (int nt = 0; nt < 2; ++nt) {
        const int col = ccol0 + nb + nt * 8 + 2 * tig;
        tb[nt][0] = Bsc[col];
        tb[nt][1] = Bsc[col + 1];
    }
    #pragma unroll
    for (int mt = 0; mt < 4; ++mt) {
        #pragma unroll
        for (int rr = 0; rr < 2; ++rr) {
            const int row = bm + mb + mt * 16 + g + rr * 8;
            const float sa = Asc[row] * INV127SQ;
            const size_t base = (size_t)row * LDC + ccol0 + nb + 2 * tig;
            #pragma unroll
            for (int nt = 0; nt < 2; ++nt) {
                const float f0 = fmaf((float)acc2[mt][nt][2 * rr],     INV254,
                                      (float)acc1[mt][nt][2 * rr]);
                const float f1 = fmaf((float)acc2[mt][nt][2 * rr + 1], INV254,
                                      (float)acc1[mt][nt][2 * rr + 1]);
                float v0 = f0 * sa * tb[nt][0];
                float v1 = f1 * sa * tb[nt][1];
                if (MODE == 0) {
                    v0 = gelu_tanh(v0) * wt;
                    v1 = gelu_tanh(v1) * wt;
                }
                *(float2*)(C + base + nt * 8) = make_float2(v0, v1);
            }
        }
    }
}

// ---------------- entry point -------------------------------------------------
extern "C" void kernel_launch(void* const* d_in, const int* in_sizes, int n_in,
                              void* d_out, int out_size)
{
    (void)in_sizes; (void)n_in; (void)out_size;
    const int*   ids = (const int*)  d_in[0];
    const float* emb = (const float*)d_in[1];
    const float* wr  = (const float*)d_in[2];
    const float* w1  = (const float*)d_in[3];
    const float* w2  = (const float*)d_in[4];
    const float* wh  = (const float*)d_in[5];
    float* out = (float*)d_out;

    cudaFuncSetAttribute(mma_gemm_kernel<0>, cudaFuncAttributeMaxDynamicSharedMemorySize, SMEM_BYTES);
    cudaFuncSetAttribute(mma_gemm_kernel<1>, cudaFuncAttributeMaxDynamicSharedMemorySize, SMEM_BYTES);
    cudaFuncSetAttribute(mma_gemm_kernel<2>, cudaFuncAttributeMaxDynamicSharedMemorySize, SMEM_BYTES);

    gather_quant_kernel<<<NTOK, 256>>>(ids, emb);
    pool_partial_kernel<<<64,   256>>>(ids, emb);
    pool_final_kernel  <<<1,    256>>>();
    router_kernel      <<<1,    512>>>(wr);

    zero_ws_kernel   <<<32, 256>>>();
    colmax_w1_kernel <<<dim3(NH / 256, 2, ND / 128), 256>>>(w1);
    colmax_w2_kernel <<<dim3(ND / 256, 2, NH / 128), 256>>>(w2);
    colmax_wh_kernel <<<NV / 256, 256>>>(wh);

    transpose_quant_kernel<<<dim3(NH / 32, ND / 32, 2), dim3(32, 8)>>>(w1, ND, NH, (long)ND * NH, 0);
    transpose_quant_kernel<<<dim3(ND / 32, NH / 32, 2), dim3(32, 8)>>>(w2, NH, ND, (long)NH * ND, 1);
    transpose_quant_kernel<<<dim3(NV / 32, ND / 32, 1), dim3(32, 8)>>>(wh, ND, NV, 0, 2);

    mma_gemm_kernel<0><<<dim3(NH / BN, NTOK / BM, 2), 256, SMEM_BYTES>>>(nullptr);
    quant_rows_kernel<0><<<NTOK, 256>>>();
    mma_gemm_kernel<1><<<dim3(ND / BN, NTOK / BM, 1), 256, SMEM_BYTES>>>(nullptr);
    quant_rows_kernel<1><<<NTOK, 256>>>();
    mma_gemm_kernel<2><<<dim3(NV / BN, NTOK / BM, 1), 256, SMEM_BYTES>>>(out);
}

// round 10
// speedup vs baseline: 2.5450x; 2.5450x over previous
#include <cuda_runtime.h>
#include <cuda_bf16.h>
#include <stdint.h>
#include <math.h>

// ---------------- problem dims ----------------------------------------------
#define NB   4
#define NL   2048
#define ND   1024
#define NH   4096
#define NV   32000
#define NEXP 16
#define NTOK (NB*NL)     // 8192
#define KCAT (2*NH)      // 8192

// ---------------- persistent bf16 hi/lo operand storage ----------------------
__device__ __nv_bfloat16 g_Xh[NTOK * ND],  g_Xl[NTOK * ND];
__device__ __nv_bfloat16 g_Hh[(size_t)NTOK * KCAT], g_Hl[(size_t)NTOK * KCAT];
__device__ __nv_bfloat16 g_Oh[NTOK * ND],  g_Ol[NTOK * ND];
__device__ __nv_bfloat16 g_w1h[(size_t)2 * NH * ND], g_w1l[(size_t)2 * NH * ND];
__device__ __nv_bfloat16 g_w2h[(size_t)ND * KCAT],   g_w2l[(size_t)ND * KCAT];
__device__ __nv_bfloat16 g_whh[(size_t)NV * ND],     g_whl[(size_t)NV * ND];
__device__ float g_pool_part[64 * ND];
__device__ float g_pool[ND];
__device__ int   g_eidx[2];
__device__ float g_ewt[2];

// ---------------- helpers -----------------------------------------------------
__device__ __forceinline__ float gelu_tanh(float x) {
    const float u = 0.7978845608028654f * (x + 0.044715f * x * x * x);
    return 0.5f * x * (1.0f + tanhf(u));
}
__device__ __forceinline__ uint32_t pkbf(__nv_bfloat16 a, __nv_bfloat16 b) {
    return (uint32_t)__bfloat16_as_ushort(a) |
           ((uint32_t)__bfloat16_as_ushort(b) << 16);
}
__device__ __forceinline__ void split2(float v, __nv_bfloat16& h, __nv_bfloat16& l) {
    h = __float2bfloat16(v);
    l = __float2bfloat16(v - __bfloat162float(h));
}
__device__ __forceinline__ uint32_t s2u(const void* p) {
    uint32_t a;
    asm("{ .reg .u64 t; cvta.to.shared.u64 t, %1; cvt.u32.u64 %0, t; }"
        : "=r"(a) : "l"(p));
    return a;
}

__device__ __forceinline__ void mma_bf16(float* d, const uint32_t* a,
                                         const uint32_t* b) {
    asm volatile(
        "mma.sync.aligned.m16n8k16.row.col.f32.bf16.bf16.f32 "
        "{%0,%1,%2,%3}, {%4,%5,%6,%7}, {%8,%9}, {%0,%1,%2,%3};"
        : "+f"(d[0]), "+f"(d[1]), "+f"(d[2]), "+f"(d[3])
        : "r"(a[0]), "r"(a[1]), "r"(a[2]), "r"(a[3]),
          "r"(b[0]), "r"(b[1]));
}

#define LDSM4(r0, r1, r2, r3, addr) \
    asm volatile("ldmatrix.sync.aligned.m8n8.x4.shared.b16 {%0,%1,%2,%3}, [%4];" \
        : "=r"(r0), "=r"(r1), "=r"(r2), "=r"(r3) : "r"(addr))

#define CPASYNC16(dst, src) \
    asm volatile("cp.async.cg.shared.global [%0], [%1], 16;" \
        :: "r"(dst), "l"(src) : "memory")
#define CPCOMMIT() asm volatile("cp.async.commit_group;" ::: "memory")
#define CPWAIT2()  asm volatile("cp.async.wait_group 2;"  ::: "memory")

// chunk swizzle: 16B chunks, ci ^ bit3->bit0 (keeps ldmatrix 8-row phases conflict-free)
#define SWZ16(ci) ((uint32_t)(((ci) ^ (((ci) >> 3) & 1)) * 16))

// ---------------- embed / pool / router --------------------------------------
__global__ void gather_split_kernel(const int* __restrict__ ids,
                                    const float* __restrict__ emb)
{
    const int t = blockIdx.x;
    const int id = ids[t];
    const int c = threadIdx.x * 4;
    float4 v = *(const float4*)(emb + (size_t)id * ND + c);
    __nv_bfloat16 h0, h1, h2, h3, l0, l1, l2, l3;
    split2(v.x, h0, l0); split2(v.y, h1, l1);
    split2(v.z, h2, l2); split2(v.w, h3, l3);
    *(uint2*)(g_Xh + (size_t)t * ND + c) = make_uint2(pkbf(h0, h1), pkbf(h2, h3));
    *(uint2*)(g_Xl + (size_t)t * ND + c) = make_uint2(pkbf(l0, l1), pkbf(l2, l3));
}

__global__ void pool_partial_kernel(const int* __restrict__ ids,
                                    const float* __restrict__ emb)
{
    __shared__ int sid[128];
    const int t0 = blockIdx.x * 128;
    if (threadIdx.x < 128) sid[threadIdx.x] = ids[t0 + threadIdx.x];
    __syncthreads();
    const int c = threadIdx.x * 4;
    float4 s = make_float4(0.f, 0.f, 0.f, 0.f);
    for (int t = 0; t < 128; ++t) {
        const float4 v = *(const float4*)(emb + (size_t)sid[t] * ND + c);
        s.x += v.x; s.y += v.y; s.z += v.z; s.w += v.w;
    }
    *(float4*)(g_pool_part + blockIdx.x * ND + c) = s;
}

__global__ void pool_final_kernel()
{
    const int c = threadIdx.x * 4;
    float4 s = make_float4(0.f, 0.f, 0.f, 0.f);
    for (int b = 0; b < 64; ++b) {
        const float4 v = *(const float4*)(g_pool_part + b * ND + c);
        s.x += v.x; s.y += v.y; s.z += v.z; s.w += v.w;
    }
    const float inv = 1.0f / (float)NTOK;
    s.x *= inv; s.y *= inv; s.z *= inv; s.w *= inv;
    *(float4*)(g_pool + c) = s;
}

__global__ void router_kernel(const float* __restrict__ w_router)
{
    __shared__ float slog[NEXP];
    const int warp = threadIdx.x >> 5;
    const int lane = threadIdx.x & 31;
    float s = 0.f;
    for (int d = lane; d < ND; d += 32)
        s += g_pool[d] * w_router[d * NEXP + warp];
    #pragma unroll
    for (int o = 16; o > 0; o >>= 1) s += __shfl_down_sync(0xffffffffu, s, o);
    if (lane == 0) slog[warp] = s;
    __syncthreads();
    if (threadIdx.x == 0) {
        float v0 = -1e30f, v1 = -1e30f; int i0 = 0, i1 = 0;
        for (int n = 0; n < NEXP; ++n) {
            const float l = slog[n];
            if (l > v0) { v1 = v0; i1 = i0; v0 = l; i0 = n; }
            else if (l > v1) { v1 = l; i1 = n; }
        }
        const float e1  = expf(v1 - v0);
        const float den = 1.0f + e1;
        g_eidx[0] = i0; g_eidx[1] = i1;
        g_ewt[0] = 1.0f / den; g_ewt[1] = e1 / den;
    }
}

// ---------------- weight transpose + split ------------------------------------
__global__ void transpose_split_kernel(const float* __restrict__ src,
                                       int K, int N, long src_z, int mode)
{
    __shared__ float tile[32][33];
    const int e = blockIdx.z;
    __nv_bfloat16 *dh, *dl; long dst_z; int ld; int use_e;
    if (mode == 0)      { dh = g_w1h; dl = g_w1l; dst_z = (long)NH * ND; ld = ND;   use_e = 1; }
    else if (mode == 1) { dh = g_w2h; dl = g_w2l; dst_z = NH;            ld = KCAT; use_e = 1; }
    else                { dh = g_whh; dl = g_whl; dst_z = 0;             ld = ND;   use_e = 0; }

    const int sel = use_e ? g_eidx[e] : e;
    const float* in = src + (size_t)sel * src_z;
    dh += (size_t)e * dst_z;
    dl += (size_t)e * dst_z;

    const int n0 = blockIdx.x * 32, k0 = blockIdx.y * 32;
    const int tx = threadIdx.x, ty = threadIdx.y;   // (32, 8)
    #pragma unroll
    for (int j = 0; j < 32; j += 8)
        tile[ty + j][tx] = in[(size_t)(k0 + ty + j) * N + n0 + tx];
    __syncthreads();
    #pragma unroll
    for (int j = 0; j < 32; j += 8) {
        const float v = tile[tx][ty + j];
        __nv_bfloat16 h, l; split2(v, h, l);
        const size_t o = (size_t)(n0 + ty + j) * ld + k0 + tx;
        dh[o] = h; dl[o] = l;
    }
}

// ---------------- bf16-split mma.sync GEMM -------------------------------------
// 128-thread CTA, 4 warps in 2x2, warp tile 64x64, 4-stage cp.async, 2 CTAs/SM.
#define BM 128
#define BN 128
#define BK 16
#define NSTAGE 4
// per-stage: AH[128x32B] AL BH[128x32B] BL
#define OFF_AL 4096
#define OFF_BH 8192
#define OFF_BL 12288
#define STAGE  16384
#define SMEM_BYTES (NSTAGE * STAGE)   // 65536 per CTA; 2 CTAs = 128KB/SM

// MODE 0: H = gelu(X @ w1t[e]^T)*wt[e] -> Hh/Hl   (grid.z = expert)
// MODE 1: O = H @ w2t^T -> Oh/Ol
// MODE 2: LOGITS = O @ wht^T -> fp32 out
template<int MODE>
__global__ void __launch_bounds__(128, 2)
mma_gemm_kernel(float* __restrict__ Cext)
{
    constexpr int K   = (MODE == 1) ? KCAT : ND;
    constexpr int NT  = K / BK;
    constexpr int LDC = (MODE == 0) ? KCAT : ((MODE == 1) ? ND : NV);

    const __nv_bfloat16 *Ah, *Al, *Bh_, *Bl_;
    if (MODE == 0)      { Ah = g_Xh; Al = g_Xl; Bh_ = g_w1h; Bl_ = g_w1l; }
    else if (MODE == 1) { Ah = g_Hh; Al = g_Hl; Bh_ = g_w2h; Bl_ = g_w2l; }
    else                { Ah = g_Oh; Al = g_Ol; Bh_ = g_whh; Bl_ = g_whl; }

    extern __shared__ __align__(16) uint8_t smraw[];
    const uint32_t smb = s2u(smraw);

    const int tid  = threadIdx.x;
    const int w    = tid >> 5, lane = tid & 31;
    const int g    = lane >> 2, tig = lane & 3;
    const int mb   = (w >> 1) * 64;        // 2 m-warps
    const int nb   = (w & 1) * 64;         // 2 n-warps
    const int bm   = blockIdx.y * BM;
    const int bn   = blockIdx.x * BN;

    float wt = 1.f; int ccol0 = bn;
    if (MODE == 0) {
        const int e = blockIdx.z;
        wt    = g_ewt[e];
        Bh_  += (size_t)e * NH * ND;
        Bl_  += (size_t)e * NH * ND;
        ccol0 = e * NH + bn;
    }

    const __nv_bfloat16* Ab_h = Ah + (size_t)bm * K;
    const __nv_bfloat16* Ab_l = Al + (size_t)bm * K;
    const __nv_bfloat16* Bb_h = Bh_ + (size_t)bn * K;
    const __nv_bfloat16* Bb_l = Bl_ + (size_t)bn * K;

    // fill: 1024 16B chunks / 128 threads = 8 each (2 per region)
    auto fill = [&](uint32_t sbase, int k0) {
        #pragma unroll
        for (int i = 0; i < 2; ++i) {
            const int ci = i * 128 + tid;
            const size_t go = (size_t)(ci >> 1) * K + k0 + (ci & 1) * 8;
            CPASYNC16(sbase + SWZ16(ci),          Ab_h + go);
            CPASYNC16(sbase + OFF_AL + SWZ16(ci), Ab_l + go);
            CPASYNC16(sbase + OFF_BH + SWZ16(ci), Bb_h + go);
            CPASYNC16(sbase + OFF_BL + SWZ16(ci), Bb_l + go);
        }
    };

    // ldmatrix lane offsets (verified mapping, rounds 5/6)
    const int am = lane >> 3;
    const int a_ci0 = (mb + ((am & 1) << 3) + (lane & 7)) * 2 + (am >> 1);
    const uint32_t aoff = SWZ16(a_ci0);
    const int bmm = lane >> 3;
    const int b_ci0 = (nb + ((bmm >> 1) << 3) + (lane & 7)) * 2 + (bmm & 1);
    const uint32_t boff = SWZ16(b_ci0);

    float acc[4][8][4];
    #pragma unroll
    for (int i = 0; i < 4; ++i)
        #pragma unroll
        for (int j = 0; j < 8; ++j)
            #pragma unroll
            for (int q = 0; q < 4; ++q) acc[i][j][q] = 0.f;

    // prologue: stages 0,1,2 in flight
    fill(smb, 0);                  CPCOMMIT();
    fill(smb + STAGE, BK);         CPCOMMIT();
    fill(smb + 2 * STAGE, 2 * BK); CPCOMMIT();

    int rd = 0, wr = 3;
    #pragma unroll 1
    for (int t = 0; t < NT; ++t) {
        CPWAIT2();
        __syncthreads();

        const uint32_t sb = smb + rd * STAGE;

        // B fragments for all 8 n-tiles (hi + lo)
        uint32_t Bhf[8][2], Blf[8][2];
        #pragma unroll
        for (int p = 0; p < 4; ++p) {
            uint32_t r0, r1, r2, r3;
            LDSM4(r0, r1, r2, r3, sb + OFF_BH + boff + p * 512);
            Bhf[2*p][0] = r0; Bhf[2*p][1] = r1;
            Bhf[2*p+1][0] = r2; Bhf[2*p+1][1] = r3;
            LDSM4(r0, r1, r2, r3, sb + OFF_BL + boff + p * 512);
            Blf[2*p][0] = r0; Blf[2*p][1] = r1;
            Blf[2*p+1][0] = r2; Blf[2*p+1][1] = r3;
        }

        if (t + 3 < NT) fill(smb + wr * STAGE, (t + 3) * BK);
        CPCOMMIT();

        #pragma unroll
        for (int mt = 0; mt < 4; ++mt) {
            uint32_t Ahf[4], Alf[4];
            LDSM4(Ahf[0], Ahf[1], Ahf[2], Ahf[3], sb + aoff + mt * 512);
            LDSM4(Alf[0], Alf[1], Alf[2], Alf[3], sb + OFF_AL + aoff + mt * 512);
            #pragma unroll
            for (int nt = 0; nt < 8; ++nt) {
                mma_bf16(acc[mt][nt], Ahf, Bhf[nt]);
                mma_bf16(acc[mt][nt], Ahf, Blf[nt]);
                mma_bf16(acc[mt][nt], Alf, Bhf[nt]);
            }
        }

        rd = (rd + 1) & 3;
        wr = (wr + 1) & 3;
    }

    // ---- epilogue ----
    #pragma unroll
    for (int mt = 0; mt < 4; ++mt) {
        const int row0 = bm + mb + mt * 16 + g;
        #pragma unroll
        for (int rr = 0; rr < 2; ++rr) {
            const int row = row0 + rr * 8;
            const size_t base = (size_t)row * LDC + ccol0 + nb + 2 * tig;
            #pragma unroll
            for (int nt = 0; nt < 8; ++nt) {
                float v0 = acc[mt][nt][2 * rr];
                float v1 = acc[mt][nt][2 * rr + 1];
                if (MODE == 0) {
                    v0 = gelu_tanh(v0) * wt;
                    v1 = gelu_tanh(v1) * wt;
                }
                if (MODE == 2) {
                    *(float2*)(Cext + base + nt * 8) = make_float2(v0, v1);
                } else {
                    __nv_bfloat16 h0, l0, h1, l1;
                    split2(v0, h0, l0); split2(v1, h1, l1);
                    __nv_bfloat16* dh = (MODE == 0) ? g_Hh : g_Oh;
                    __nv_bfloat16* dl = (MODE == 0) ? g_Hl : g_Ol;
                    *(uint32_t*)(dh + base + nt * 8) = pkbf(h0, h1);
                    *(uint32_t*)(dl + base + nt * 8) = pkbf(l0, l1);
                }
            }
        }
    }
}

// ---------------- entry point -------------------------------------------------
extern "C" void kernel_launch(void* const* d_in, const int* in_sizes, int n_in,
                              void* d_out, int out_size)
{
    (void)in_sizes; (void)n_in; (void)out_size;
    const int*   ids = (const int*)  d_in[0];
    const float* emb = (const float*)d_in[1];
    const float* wr  = (const float*)d_in[2];
    const float* w1  = (const float*)d_in[3];
    const float* w2  = (const float*)d_in[4];
    const float* wh  = (const float*)d_in[5];
    float* out = (float*)d_out;

    cudaFuncSetAttribute(mma_gemm_kernel<0>, cudaFuncAttributeMaxDynamicSharedMemorySize, SMEM_BYTES);
    cudaFuncSetAttribute(mma_gemm_kernel<1>, cudaFuncAttributeMaxDynamicSharedMemorySize, SMEM_BYTES);
    cudaFuncSetAttribute(mma_gemm_kernel<2>, cudaFuncAttributeMaxDynamicSharedMemorySize, SMEM_BYTES);

    gather_split_kernel<<<NTOK, 256>>>(ids, emb);
    pool_partial_kernel<<<64,   256>>>(ids, emb);
    pool_final_kernel  <<<1,    256>>>();
    router_kernel      <<<1,    512>>>(wr);

    transpose_split_kernel<<<dim3(NH / 32, ND / 32, 2), dim3(32, 8)>>>(w1, ND, NH, (long)ND * NH, 0);
    transpose_split_kernel<<<dim3(ND / 32, NH / 32, 2), dim3(32, 8)>>>(w2, NH, ND, (long)NH * ND, 1);
    transpose_split_kernel<<<dim3(NV / 32, ND / 32, 1), dim3(32, 8)>>>(wh, ND, NV, 0, 2);

    mma_gemm_kernel<0><<<dim3(NH / BN, NTOK / BM, 2), 128, SMEM_BYTES>>>(nullptr);
    mma_gemm_kernel<1><<<dim3(ND / BN, NTOK / BM, 1), 128, SMEM_BYTES>>>(nullptr);
    mma_gemm_kernel<2><<<dim3(NV / BN, NTOK / BM, 1), 128, SMEM_BYTES>>>(out);
}

// round 11
// speedup vs baseline: 3.5845x; 1.4084x over previous
#include <cuda_runtime.h>
#include <cuda_fp16.h>
#include <stdint.h>
#include <math.h>

// ---------------- problem dims ----------------------------------------------
#define NB   4
#define NL   2048
#define ND   1024
#define NH   4096
#define NV   32000
#define NEXP 16
#define NTOK (NB*NL)     // 8192
#define KCAT (2*NH)      // 8192

#define ASCALE 1024.0f
#define INVS   (1.0f/1024.0f)

// ---------------- persistent fp16 operand storage ----------------------------
// token-side operands (A) carry x1024 scale, split into hi/lo fp16 digits
__device__ __half g_Xh[NTOK * ND],  g_Xl[NTOK * ND];
__device__ __half g_Hh[(size_t)NTOK * KCAT], g_Hl[(size_t)NTOK * KCAT];
__device__ __half g_Oh[NTOK * ND],  g_Ol[NTOK * ND];
// weight-side operands (B): single fp16, unscaled
__device__ __half g_w1f[(size_t)2 * NH * ND];
__device__ __half g_w2f[(size_t)ND * KCAT];
__device__ __half g_whf[(size_t)NV * ND];
__device__ float g_pool_part[64 * ND];
__device__ float g_pool[ND];
__device__ int   g_eidx[2];
__device__ float g_ewt[2];

// ---------------- helpers -----------------------------------------------------
__device__ __forceinline__ float gelu_tanh(float x) {
    const float u = 0.7978845608028654f * (x + 0.044715f * x * x * x);
    return 0.5f * x * (1.0f + tanhf(u));
}
__device__ __forceinline__ uint32_t pkh(__half a, __half b) {
    return (uint32_t)__half_as_ushort(a) |
           ((uint32_t)__half_as_ushort(b) << 16);
}
__device__ __forceinline__ void split2h(float v, __half& h, __half& l) {
    h = __float2half_rn(v);
    l = __float2half_rn(v - __half2float(h));
}
__device__ __forceinline__ uint32_t s2u(const void* p) {
    uint32_t a;
    asm("{ .reg .u64 t; cvta.to.shared.u64 t, %1; cvt.u32.u64 %0, t; }"
        : "=r"(a) : "l"(p));
    return a;
}

__device__ __forceinline__ void mma_f16(float* d, const uint32_t* a,
                                        const uint32_t* b) {
    asm volatile(
        "mma.sync.aligned.m16n8k16.row.col.f32.f16.f16.f32 "
        "{%0,%1,%2,%3}, {%4,%5,%6,%7}, {%8,%9}, {%0,%1,%2,%3};"
        : "+f"(d[0]), "+f"(d[1]), "+f"(d[2]), "+f"(d[3])
        : "r"(a[0]), "r"(a[1]), "r"(a[2]), "r"(a[3]),
          "r"(b[0]), "r"(b[1]));
}

#define LDSM4(r0, r1, r2, r3, addr) \
    asm volatile("ldmatrix.sync.aligned.m8n8.x4.shared.b16 {%0,%1,%2,%3}, [%4];" \
        : "=r"(r0), "=r"(r1), "=r"(r2), "=r"(r3) : "r"(addr))

#define CPASYNC16(dst, src) \
    asm volatile("cp.async.cg.shared.global [%0], [%1], 16;" \
        :: "r"(dst), "l"(src) : "memory")
#define CPCOMMIT() asm volatile("cp.async.commit_group;" ::: "memory")
#define CPWAIT2()  asm volatile("cp.async.wait_group 2;"  ::: "memory")

// chunk swizzle: 16B chunks, ci ^ bit3->bit0 (keeps ldmatrix 8-row phases conflict-free)
#define SWZ16(ci) ((uint32_t)(((ci) ^ (((ci) >> 3) & 1)) * 16))

// ---------------- embed / pool / router --------------------------------------
__global__ void gather_split_kernel(const int* __restrict__ ids,
                                    const float* __restrict__ emb)
{
    const int t = blockIdx.x;
    const int id = ids[t];
    const int c = threadIdx.x * 4;
    float4 v = *(const float4*)(emb + (size_t)id * ND + c);
    __half h0, h1, h2, h3, l0, l1, l2, l3;
    split2h(v.x * ASCALE, h0, l0); split2h(v.y * ASCALE, h1, l1);
    split2h(v.z * ASCALE, h2, l2); split2h(v.w * ASCALE, h3, l3);
    *(uint2*)(g_Xh + (size_t)t * ND + c) = make_uint2(pkh(h0, h1), pkh(h2, h3));
    *(uint2*)(g_Xl + (size_t)t * ND + c) = make_uint2(pkh(l0, l1), pkh(l2, l3));
}

__global__ void pool_partial_kernel(const int* __restrict__ ids,
                                    const float* __restrict__ emb)
{
    __shared__ int sid[128];
    const int t0 = blockIdx.x * 128;
    if (threadIdx.x < 128) sid[threadIdx.x] = ids[t0 + threadIdx.x];
    __syncthreads();
    const int c = threadIdx.x * 4;
    float4 s = make_float4(0.f, 0.f, 0.f, 0.f);
    for (int t = 0; t < 128; ++t) {
        const float4 v = *(const float4*)(emb + (size_t)sid[t] * ND + c);
        s.x += v.x; s.y += v.y; s.z += v.z; s.w += v.w;
    }
    *(float4*)(g_pool_part + blockIdx.x * ND + c) = s;
}

__global__ void pool_final_kernel()
{
    const int c = threadIdx.x * 4;
    float4 s = make_float4(0.f, 0.f, 0.f, 0.f);
    for (int b = 0; b < 64; ++b) {
        const float4 v = *(const float4*)(g_pool_part + b * ND + c);
        s.x += v.x; s.y += v.y; s.z += v.z; s.w += v.w;
    }
    const float inv = 1.0f / (float)NTOK;
    s.x *= inv; s.y *= inv; s.z *= inv; s.w *= inv;
    *(float4*)(g_pool + c) = s;
}

__global__ void router_kernel(const float* __restrict__ w_router)
{
    __shared__ float slog[NEXP];
    const int warp = threadIdx.x >> 5;
    const int lane = threadIdx.x & 31;
    float s = 0.f;
    for (int d = lane; d < ND; d += 32)
        s += g_pool[d] * w_router[d * NEXP + warp];
    #pragma unroll
    for (int o = 16; o > 0; o >>= 1) s += __shfl_down_sync(0xffffffffu, s, o);
    if (lane == 0) slog[warp] = s;
    __syncthreads();
    if (threadIdx.x == 0) {
        float v0 = -1e30f, v1 = -1e30f; int i0 = 0, i1 = 0;
        for (int n = 0; n < NEXP; ++n) {
            const float l = slog[n];
            if (l > v0) { v1 = v0; i1 = i0; v0 = l; i0 = n; }
            else if (l > v1) { v1 = l; i1 = n; }
        }
        const float e1  = expf(v1 - v0);
        const float den = 1.0f + e1;
        g_eidx[0] = i0; g_eidx[1] = i1;
        g_ewt[0] = 1.0f / den; g_ewt[1] = e1 / den;
    }
}

// ---------------- weight transpose (fp16 single) -------------------------------
// mode 0: w1[eidx[e]] (D,H) -> g_w1f + e*NH*ND  [h][d]
// mode 1: w2[eidx[e]] (H,D) -> g_w2f cols e*NH  [d][e*NH+h], ld=KCAT
// mode 2: w_head      (D,V) -> g_whf            [v][d]
__global__ void transpose_half_kernel(const float* __restrict__ src,
                                      int K, int N, long src_z, int mode)
{
    __shared__ float tile[32][33];
    const int e = blockIdx.z;
    __half* dh; long dst_z; int ld; int use_e;
    if (mode == 0)      { dh = g_w1f; dst_z = (long)NH * ND; ld = ND;   use_e = 1; }
    else if (mode == 1) { dh = g_w2f; dst_z = NH;            ld = KCAT; use_e = 1; }
    else                { dh = g_whf; dst_z = 0;             ld = ND;   use_e = 0; }

    const int sel = use_e ? g_eidx[e] : e;
    const float* in = src + (size_t)sel * src_z;
    dh += (size_t)e * dst_z;

    const int n0 = blockIdx.x * 32, k0 = blockIdx.y * 32;
    const int tx = threadIdx.x, ty = threadIdx.y;   // (32, 8)
    #pragma unroll
    for (int j = 0; j < 32; j += 8)
        tile[ty + j][tx] = in[(size_t)(k0 + ty + j) * N + n0 + tx];
    __syncthreads();
    #pragma unroll
    for (int j = 0; j < 32; j += 8)
        dh[(size_t)(n0 + ty + j) * ld + k0 + tx] =
            __float2half_rn(tile[tx][ty + j]);
}

// ---------------- fp16 2-product mma GEMM --------------------------------------
// C = (Ah + Al) @ Bh^T : A two-digit fp16 (x1024), B single fp16. 2 MMAs/tile.
// 128-thread CTA, 4 warps 2x2, warp tile 64x64, 4-stage cp.async, 2 CTAs/SM.
#define BM 128
#define BN 128
#define BK 16
#define NSTAGE 4
// per-stage: AH[128x32B] AL[128x32B] BH[128x32B]
#define OFF_AL 4096
#define OFF_BH 8192
#define STAGE  12288
#define SMEM_BYTES (NSTAGE * STAGE)   // 49152 per CTA; 2 CTAs = 96KB/SM

// MODE 0: H = gelu(X @ w1t[e]^T)*wt[e] -> Hh/Hl   (grid.z = expert)
// MODE 1: O = H @ w2t^T -> Oh/Ol
// MODE 2: LOGITS = O @ wht^T -> fp32 out
template<int MODE>
__global__ void __launch_bounds__(128, 2)
mma_gemm_kernel(float* __restrict__ Cext)
{
    constexpr int K   = (MODE == 1) ? KCAT : ND;
    constexpr int NT  = K / BK;
    constexpr int LDC = (MODE == 0) ? KCAT : ((MODE == 1) ? ND : NV);

    const __half *Ah, *Al, *Bh_;
    if (MODE == 0)      { Ah = g_Xh; Al = g_Xl; Bh_ = g_w1f; }
    else if (MODE == 1) { Ah = g_Hh; Al = g_Hl; Bh_ = g_w2f; }
    else                { Ah = g_Oh; Al = g_Ol; Bh_ = g_whf; }

    extern __shared__ __align__(16) uint8_t smraw[];
    const uint32_t smb = s2u(smraw);

    const int tid  = threadIdx.x;
    const int w    = tid >> 5, lane = tid & 31;
    const int g    = lane >> 2, tig = lane & 3;
    const int mb   = (w >> 1) * 64;        // 2 m-warps
    const int nb   = (w & 1) * 64;         // 2 n-warps
    const int bm   = blockIdx.y * BM;
    const int bn   = blockIdx.x * BN;

    float wt = 1.f; int ccol0 = bn;
    if (MODE == 0) {
        const int e = blockIdx.z;
        wt    = g_ewt[e];
        Bh_  += (size_t)e * NH * ND;
        ccol0 = e * NH + bn;
    }

    const __half* Ab_h = Ah + (size_t)bm * K;
    const __half* Ab_l = Al + (size_t)bm * K;
    const __half* Bb_h = Bh_ + (size_t)bn * K;

    // fill: 768 16B chunks / 128 threads = 6 each (2 per region)
    auto fill = [&](uint32_t sbase, int k0) {
        #pragma unroll
        for (int i = 0; i < 2; ++i) {
            const int ci = i * 128 + tid;
            const size_t go = (size_t)(ci >> 1) * K + k0 + (ci & 1) * 8;
            CPASYNC16(sbase + SWZ16(ci),          Ab_h + go);
            CPASYNC16(sbase + OFF_AL + SWZ16(ci), Ab_l + go);
            CPASYNC16(sbase + OFF_BH + SWZ16(ci), Bb_h + go);
        }
    };

    // ldmatrix lane offsets (verified mapping, rounds 5/6/9)
    const int am = lane >> 3;
    const int a_ci0 = (mb + ((am & 1) << 3) + (lane & 7)) * 2 + (am >> 1);
    const uint32_t aoff = SWZ16(a_ci0);
    const int bmm = lane >> 3;
    const int b_ci0 = (nb + ((bmm >> 1) << 3) + (lane & 7)) * 2 + (bmm & 1);
    const uint32_t boff = SWZ16(b_ci0);

    float acc[4][8][4];
    #pragma unroll
    for (int i = 0; i < 4; ++i)
        #pragma unroll
        for (int j = 0; j < 8; ++j)
            #pragma unroll
            for (int q = 0; q < 4; ++q) acc[i][j][q] = 0.f;

    // prologue: stages 0,1,2 in flight
    fill(smb, 0);                  CPCOMMIT();
    fill(smb + STAGE, BK);         CPCOMMIT();
    fill(smb + 2 * STAGE, 2 * BK); CPCOMMIT();

    int rd = 0, wr = 3;
    #pragma unroll 1
    for (int t = 0; t < NT; ++t) {
        CPWAIT2();
        __syncthreads();

        const uint32_t sb = smb + rd * STAGE;

        // B fragments for all 8 n-tiles
        uint32_t Bhf[8][2];
        #pragma unroll
        for (int p = 0; p < 4; ++p) {
            uint32_t r0, r1, r2, r3;
            LDSM4(r0, r1, r2, r3, sb + OFF_BH + boff + p * 512);
            Bhf[2*p][0] = r0; Bhf[2*p][1] = r1;
            Bhf[2*p+1][0] = r2; Bhf[2*p+1][1] = r3;
        }

        if (t + 3 < NT) fill(smb + wr * STAGE, (t + 3) * BK);
        CPCOMMIT();

        #pragma unroll
        for (int mt = 0; mt < 4; ++mt) {
            uint32_t Ahf[4], Alf[4];
            LDSM4(Ahf[0], Ahf[1], Ahf[2], Ahf[3], sb + aoff + mt * 512);
            LDSM4(Alf[0], Alf[1], Alf[2], Alf[3], sb + OFF_AL + aoff + mt * 512);
            #pragma unroll
            for (int nt = 0; nt < 8; ++nt) {
                mma_f16(acc[mt][nt], Ahf, Bhf[nt]);
                mma_f16(acc[mt][nt], Alf, Bhf[nt]);
            }
        }

        rd = (rd + 1) & 3;
        wr = (wr + 1) & 3;
    }

    // ---- epilogue (acc carries x1024 scale from A) ----
    #pragma unroll
    for (int mt = 0; mt < 4; ++mt) {
        const int row0 = bm + mb + mt * 16 + g;
        #pragma unroll
        for (int rr = 0; rr < 2; ++rr) {
            const int row = row0 + rr * 8;
            const size_t base = (size_t)row * LDC + ccol0 + nb + 2 * tig;
            #pragma unroll
            for (int nt = 0; nt < 8; ++nt) {
                float v0 = acc[mt][nt][2 * rr];
                float v1 = acc[mt][nt][2 * rr + 1];
                if (MODE == 0) {   // true value, gelu, re-apply scale
                    v0 = gelu_tanh(v0 * INVS) * wt * ASCALE;
                    v1 = gelu_tanh(v1 * INVS) * wt * ASCALE;
                }
                if (MODE == 2) {
                    *(float2*)(Cext + base + nt * 8) =
                        make_float2(v0 * INVS, v1 * INVS);
                } else {
                    // MODE 0/1: store scaled value split into fp16 digits
                    __half h0, l0, h1, l1;
                    split2h(v0, h0, l0); split2h(v1, h1, l1);
                    __half* dh = (MODE == 0) ? g_Hh : g_Oh;
                    __half* dl = (MODE == 0) ? g_Hl : g_Ol;
                    *(uint32_t*)(dh + base + nt * 8) = pkh(h0, h1);
                    *(uint32_t*)(dl + base + nt * 8) = pkh(l0, l1);
                }
            }
        }
    }
}

// ---------------- entry point -------------------------------------------------
extern "C" void kernel_launch(void* const* d_in, const int* in_sizes, int n_in,
                              void* d_out, int out_size)
{
    (void)in_sizes; (void)n_in; (void)out_size;
    const int*   ids = (const int*)  d_in[0];
    const float* emb = (const float*)d_in[1];
    const float* wr  = (const float*)d_in[2];
    const float* w1  = (const float*)d_in[3];
    const float* w2  = (const float*)d_in[4];
    const float* wh  = (const float*)d_in[5];
    float* out = (float*)d_out;

    cudaFuncSetAttribute(mma_gemm_kernel<0>, cudaFuncAttributeMaxDynamicSharedMemorySize, SMEM_BYTES);
    cudaFuncSetAttribute(mma_gemm_kernel<1>, cudaFuncAttributeMaxDynamicSharedMemorySize, SMEM_BYTES);
    cudaFuncSetAttribute(mma_gemm_kernel<2>, cudaFuncAttributeMaxDynamicSharedMemorySize, SMEM_BYTES);

    gather_split_kernel<<<NTOK, 256>>>(ids, emb);
    pool_partial_kernel<<<64,   256>>>(ids, emb);
    pool_final_kernel  <<<1,    256>>>();
    router_kernel      <<<1,    512>>>(wr);

    transpose_half_kernel<<<dim3(NH / 32, ND / 32, 2), dim3(32, 8)>>>(w1, ND, NH, (long)ND * NH, 0);
    transpose_half_kernel<<<dim3(ND / 32, NH / 32, 2), dim3(32, 8)>>>(w2, NH, ND, (long)NH * ND, 1);
    transpose_half_kernel<<<dim3(NV / 32, ND / 32, 1), dim3(32, 8)>>>(wh, ND, NV, 0, 2);

    mma_gemm_kernel<0><<<dim3(NH / BN, NTOK / BM, 2), 128, SMEM_BYTES>>>(nullptr);
    mma_gemm_kernel<1><<<dim3(ND / BN, NTOK / BM, 1), 128, SMEM_BYTES>>>(nullptr);
    mma_gemm_kernel<2><<<dim3(NV / BN, NTOK / BM, 1), 128, SMEM_BYTES>>>(out);
}

// round 12
// speedup vs baseline: 5.1991x; 1.4505x over previous
#include <cuda_runtime.h>
#include <cuda_fp16.h>
#include <stdint.h>
#include <math.h>

// ---------------- problem dims ----------------------------------------------
#define NB   4
#define NL   2048
#define ND   1024
#define NH   4096
#define NV   32000
#define NEXP 16
#define NTOK (NB*NL)     // 8192
#define KCAT (2*NH)      // 8192

#define ASCALE 1024.0f
#define INVS   (1.0f/1024.0f)

// ---------------- persistent fp16 operand storage ----------------------------
// token-side operands carry x1024 scale; X,H two-digit; O single-digit
__device__ __half g_Xh[NTOK * ND],  g_Xl[NTOK * ND];
__device__ __half g_Hh[(size_t)NTOK * KCAT], g_Hl[(size_t)NTOK * KCAT];
__device__ __half g_Oh[NTOK * ND];
// weight-side operands (B): single fp16, unscaled
__device__ __half g_w1f[(size_t)2 * NH * ND];
__device__ __half g_w2f[(size_t)ND * KCAT];
__device__ __half g_whf[(size_t)NV * ND];
__device__ float g_pool_part[64 * ND];
__device__ float g_pool[ND];
__device__ int   g_eidx[2];
__device__ float g_ewt[2];

// ---------------- helpers -----------------------------------------------------
__device__ __forceinline__ float gelu_tanh(float x) {
    const float u = 0.7978845608028654f * (x + 0.044715f * x * x * x);
    return 0.5f * x * (1.0f + tanhf(u));
}
__device__ __forceinline__ uint32_t pkh(__half a, __half b) {
    return (uint32_t)__half_as_ushort(a) |
           ((uint32_t)__half_as_ushort(b) << 16);
}
__device__ __forceinline__ void split2h(float v, __half& h, __half& l) {
    h = __float2half_rn(v);
    l = __float2half_rn(v - __half2float(h));
}
__device__ __forceinline__ uint32_t s2u(const void* p) {
    uint32_t a;
    asm("{ .reg .u64 t; cvta.to.shared.u64 t, %1; cvt.u32.u64 %0, t; }"
        : "=r"(a) : "l"(p));
    return a;
}

__device__ __forceinline__ void mma_f16(float* d, const uint32_t* a,
                                        const uint32_t* b) {
    asm volatile(
        "mma.sync.aligned.m16n8k16.row.col.f32.f16.f16.f32 "
        "{%0,%1,%2,%3}, {%4,%5,%6,%7}, {%8,%9}, {%0,%1,%2,%3};"
        : "+f"(d[0]), "+f"(d[1]), "+f"(d[2]), "+f"(d[3])
        : "r"(a[0]), "r"(a[1]), "r"(a[2]), "r"(a[3]),
          "r"(b[0]), "r"(b[1]));
}

#define LDSM4(r0, r1, r2, r3, addr) \
    asm volatile("ldmatrix.sync.aligned.m8n8.x4.shared.b16 {%0,%1,%2,%3}, [%4];" \
        : "=r"(r0), "=r"(r1), "=r"(r2), "=r"(r3) : "r"(addr))

#define CPASYNC16(dst, src) \
    asm volatile("cp.async.cg.shared.global [%0], [%1], 16;" \
        :: "r"(dst), "l"(src) : "memory")
#define CPCOMMIT() asm volatile("cp.async.commit_group;" ::: "memory")
#define CPWAIT2()  asm volatile("cp.async.wait_group 2;"  ::: "memory")

// chunk swizzle: 16B chunks, ci ^ bit3->bit0 (keeps ldmatrix 8-row phases conflict-free)
#define SWZ16(ci) ((uint32_t)(((ci) ^ (((ci) >> 3) & 1)) * 16))

// ---------------- embed / pool / router --------------------------------------
__global__ void gather_split_kernel(const int* __restrict__ ids,
                                    const float* __restrict__ emb)
{
    const int t = blockIdx.x;
    const int id = ids[t];
    const int c = threadIdx.x * 4;
    float4 v = *(const float4*)(emb + (size_t)id * ND + c);
    __half h0, h1, h2, h3, l0, l1, l2, l3;
    split2h(v.x * ASCALE, h0, l0); split2h(v.y * ASCALE, h1, l1);
    split2h(v.z * ASCALE, h2, l2); split2h(v.w * ASCALE, h3, l3);
    *(uint2*)(g_Xh + (size_t)t * ND + c) = make_uint2(pkh(h0, h1), pkh(h2, h3));
    *(uint2*)(g_Xl + (size_t)t * ND + c) = make_uint2(pkh(l0, l1), pkh(l2, l3));
}

__global__ void pool_partial_kernel(const int* __restrict__ ids,
                                    const float* __restrict__ emb)
{
    __shared__ int sid[128];
    const int t0 = blockIdx.x * 128;
    if (threadIdx.x < 128) sid[threadIdx.x] = ids[t0 + threadIdx.x];
    __syncthreads();
    const int c = threadIdx.x * 4;
    float4 s = make_float4(0.f, 0.f, 0.f, 0.f);
    for (int t = 0; t < 128; ++t) {
        const float4 v = *(const float4*)(emb + (size_t)sid[t] * ND + c);
        s.x += v.x; s.y += v.y; s.z += v.z; s.w += v.w;
    }
    *(float4*)(g_pool_part + blockIdx.x * ND + c) = s;
}

__global__ void pool_final_kernel()
{
    const int c = threadIdx.x * 4;
    float4 s = make_float4(0.f, 0.f, 0.f, 0.f);
    for (int b = 0; b < 64; ++b) {
        const float4 v = *(const float4*)(g_pool_part + b * ND + c);
        s.x += v.x; s.y += v.y; s.z += v.z; s.w += v.w;
    }
    const float inv = 1.0f / (float)NTOK;
    s.x *= inv; s.y *= inv; s.z *= inv; s.w *= inv;
    *(float4*)(g_pool + c) = s;
}

__global__ void router_kernel(const float* __restrict__ w_router)
{
    __shared__ float slog[NEXP];
    const int warp = threadIdx.x >> 5;
    const int lane = threadIdx.x & 31;
    float s = 0.f;
    for (int d = lane; d < ND; d += 32)
        s += g_pool[d] * w_router[d * NEXP + warp];
    #pragma unroll
    for (int o = 16; o > 0; o >>= 1) s += __shfl_down_sync(0xffffffffu, s, o);
    if (lane == 0) slog[warp] = s;
    __syncthreads();
    if (threadIdx.x == 0) {
        float v0 = -1e30f, v1 = -1e30f; int i0 = 0, i1 = 0;
        for (int n = 0; n < NEXP; ++n) {
            const float l = slog[n];
            if (l > v0) { v1 = v0; i1 = i0; v0 = l; i0 = n; }
            else if (l > v1) { v1 = l; i1 = n; }
        }
        const float e1  = expf(v1 - v0);
        const float den = 1.0f + e1;
        g_eidx[0] = i0; g_eidx[1] = i1;
        g_ewt[0] = 1.0f / den; g_ewt[1] = e1 / den;
    }
}

// ---------------- weight transpose (fp16 single) -------------------------------
__global__ void transpose_half_kernel(const float* __restrict__ src,
                                      int K, int N, long src_z, int mode)
{
    __shared__ float tile[32][33];
    const int e = blockIdx.z;
    __half* dh; long dst_z; int ld; int use_e;
    if (mode == 0)      { dh = g_w1f; dst_z = (long)NH * ND; ld = ND;   use_e = 1; }
    else if (mode == 1) { dh = g_w2f; dst_z = NH;            ld = KCAT; use_e = 1; }
    else                { dh = g_whf; dst_z = 0;             ld = ND;   use_e = 0; }

    const int sel = use_e ? g_eidx[e] : e;
    const float* in = src + (size_t)sel * src_z;
    dh += (size_t)e * dst_z;

    const int n0 = blockIdx.x * 32, k0 = blockIdx.y * 32;
    const int tx = threadIdx.x, ty = threadIdx.y;   // (32, 8)
    #pragma unroll
    for (int j = 0; j < 32; j += 8)
        tile[ty + j][tx] = in[(size_t)(k0 + ty + j) * N + n0 + tx];
    __syncthreads();
    #pragma unroll
    for (int j = 0; j < 32; j += 8)
        dh[(size_t)(n0 + ty + j) * ld + k0 + tx] =
            __float2half_rn(tile[tx][ty + j]);
}

// ---------------- fp16 mma GEMM: NPROD digits on the A side --------------------
// MODE 0/1: C = (Ah + Al) @ B^T (2 products). MODE 2: C = Ah @ B^T (1 product).
// 128-thread CTA, 4 warps 2x2, warp tile 64x64, 4-stage cp.async, 2 CTAs/SM.
#define BM 128
#define BN 128
#define BK 16
#define NSTAGE 4
#define SMEM_2P (NSTAGE * 12288)   // AH+AL+BH
#define SMEM_1P (NSTAGE * 8192)    // AH+BH

// MODE 0: H = gelu(X @ w1t[e]^T)*wt[e] -> Hh/Hl   (grid.z = expert)
// MODE 1: O = H @ w2t^T -> Oh (single digit)
// MODE 2: LOGITS = Oh @ wht^T -> fp32 out (1 product)
template<int MODE>
__global__ void __launch_bounds__(128, 2)
mma_gemm_kernel(float* __restrict__ Cext)
{
    constexpr int K     = (MODE == 1) ? KCAT : ND;
    constexpr int NT    = K / BK;
    constexpr int LDC   = (MODE == 0) ? KCAT : ((MODE == 1) ? ND : NV);
    constexpr int NPROD = (MODE == 2) ? 1 : 2;
    constexpr uint32_t OFF_AL = 4096;
    constexpr uint32_t OFF_BH = (NPROD == 2) ? 8192 : 4096;
    constexpr uint32_t STAGE  = (NPROD == 2) ? 12288 : 8192;

    const __half *Ah, *Al, *Bh_;
    if (MODE == 0)      { Ah = g_Xh; Al = g_Xl; Bh_ = g_w1f; }
    else if (MODE == 1) { Ah = g_Hh; Al = g_Hl; Bh_ = g_w2f; }
    else                { Ah = g_Oh; Al = g_Oh; Bh_ = g_whf; }

    extern __shared__ __align__(16) uint8_t smraw[];
    const uint32_t smb = s2u(smraw);

    const int tid  = threadIdx.x;
    const int w    = tid >> 5, lane = tid & 31;
    const int g    = lane >> 2, tig = lane & 3;
    const int mb   = (w >> 1) * 64;        // 2 m-warps
    const int nb   = (w & 1) * 64;         // 2 n-warps
    const int bm   = blockIdx.y * BM;
    const int bn   = blockIdx.x * BN;

    float wt = 1.f; int ccol0 = bn;
    if (MODE == 0) {
        const int e = blockIdx.z;
        wt    = g_ewt[e];
        Bh_  += (size_t)e * NH * ND;
        ccol0 = e * NH + bn;
    }

    const __half* Ab_h = Ah + (size_t)bm * K;
    const __half* Ab_l = Al + (size_t)bm * K;
    const __half* Bb_h = Bh_ + (size_t)bn * K;

    auto fill = [&](uint32_t sbase, int k0) {
        #pragma unroll
        for (int i = 0; i < 2; ++i) {
            const int ci = i * 128 + tid;
            const size_t go = (size_t)(ci >> 1) * K + k0 + (ci & 1) * 8;
            CPASYNC16(sbase + SWZ16(ci),          Ab_h + go);
            if (NPROD == 2)
                CPASYNC16(sbase + OFF_AL + SWZ16(ci), Ab_l + go);
            CPASYNC16(sbase + OFF_BH + SWZ16(ci), Bb_h + go);
        }
    };

    // ldmatrix lane offsets (verified mapping, rounds 5/6/9/10)
    const int am = lane >> 3;
    const int a_ci0 = (mb + ((am & 1) << 3) + (lane & 7)) * 2 + (am >> 1);
    const uint32_t aoff = SWZ16(a_ci0);
    const int bmm = lane >> 3;
    const int b_ci0 = (nb + ((bmm >> 1) << 3) + (lane & 7)) * 2 + (bmm & 1);
    const uint32_t boff = SWZ16(b_ci0);

    float acc[4][8][4];
    #pragma unroll
    for (int i = 0; i < 4; ++i)
        #pragma unroll
        for (int j = 0; j < 8; ++j)
            #pragma unroll
            for (int q = 0; q < 4; ++q) acc[i][j][q] = 0.f;

    // prologue: stages 0,1,2 in flight
    fill(smb, 0);                  CPCOMMIT();
    fill(smb + STAGE, BK);         CPCOMMIT();
    fill(smb + 2 * STAGE, 2 * BK); CPCOMMIT();

    int rd = 0, wr = 3;
    #pragma unroll 1
    for (int t = 0; t < NT; ++t) {
        CPWAIT2();
        __syncthreads();

        const uint32_t sb = smb + rd * STAGE;

        // B fragments for all 8 n-tiles
        uint32_t Bhf[8][2];
        #pragma unroll
        for (int p = 0; p < 4; ++p) {
            uint32_t r0, r1, r2, r3;
            LDSM4(r0, r1, r2, r3, sb + OFF_BH + boff + p * 512);
            Bhf[2*p][0] = r0; Bhf[2*p][1] = r1;
            Bhf[2*p+1][0] = r2; Bhf[2*p+1][1] = r3;
        }

        if (t + 3 < NT) fill(smb + wr * STAGE, (t + 3) * BK);
        CPCOMMIT();

        #pragma unroll
        for (int mt = 0; mt < 4; ++mt) {
            uint32_t Ahf[4], Alf[4];
            LDSM4(Ahf[0], Ahf[1], Ahf[2], Ahf[3], sb + aoff + mt * 512);
            if (NPROD == 2)
                LDSM4(Alf[0], Alf[1], Alf[2], Alf[3], sb + OFF_AL + aoff + mt * 512);
            #pragma unroll
            for (int nt = 0; nt < 8; ++nt) {
                mma_f16(acc[mt][nt], Ahf, Bhf[nt]);
                if (NPROD == 2)
                    mma_f16(acc[mt][nt], Alf, Bhf[nt]);
            }
        }

        rd = (rd + 1) & 3;
        wr = (wr + 1) & 3;
    }

    // ---- epilogue (acc carries x1024 scale from A) ----
    #pragma unroll
    for (int mt = 0; mt < 4; ++mt) {
        const int row0 = bm + mb + mt * 16 + g;
        #pragma unroll
        for (int rr = 0; rr < 2; ++rr) {
            const int row = row0 + rr * 8;
            const size_t base = (size_t)row * LDC + ccol0 + nb + 2 * tig;
            #pragma unroll
            for (int nt = 0; nt < 8; ++nt) {
                float v0 = acc[mt][nt][2 * rr];
                float v1 = acc[mt][nt][2 * rr + 1];
                if (MODE == 0) {   // true value, gelu, re-apply scale
                    v0 = gelu_tanh(v0 * INVS) * wt * ASCALE;
                    v1 = gelu_tanh(v1 * INVS) * wt * ASCALE;
                }
                if (MODE == 2) {
                    *(float2*)(Cext + base + nt * 8) =
                        make_float2(v0 * INVS, v1 * INVS);
                } else if (MODE == 1) {
                    // single-digit O store (scaled)
                    *(uint32_t*)(g_Oh + base + nt * 8) =
                        pkh(__float2half_rn(v0), __float2half_rn(v1));
                } else {
                    // MODE 0: two-digit H store (scaled)
                    __half h0, l0, h1, l1;
                    split2h(v0, h0, l0); split2h(v1, h1, l1);
                    *(uint32_t*)(g_Hh + base + nt * 8) = pkh(h0, h1);
                    *(uint32_t*)(g_Hl + base + nt * 8) = pkh(l0, l1);
                }
            }
        }
    }
}

// ---------------- entry point -------------------------------------------------
extern "C" void kernel_launch(void* const* d_in, const int* in_sizes, int n_in,
                              void* d_out, int out_size)
{
    (void)in_sizes; (void)n_in; (void)out_size;
    const int*   ids = (const int*)  d_in[0];
    const float* emb = (const float*)d_in[1];
    const float* wr  = (const float*)d_in[2];
    const float* w1  = (const float*)d_in[3];
    const float* w2  = (const float*)d_in[4];
    const float* wh  = (const float*)d_in[5];
    float* out = (float*)d_out;

    cudaFuncSetAttribute(mma_gemm_kernel<0>, cudaFuncAttributeMaxDynamicSharedMemorySize, SMEM_2P);
    cudaFuncSetAttribute(mma_gemm_kernel<1>, cudaFuncAttributeMaxDynamicSharedMemorySize, SMEM_2P);
    cudaFuncSetAttribute(mma_gemm_kernel<2>, cudaFuncAttributeMaxDynamicSharedMemorySize, SMEM_1P);

    gather_split_kernel<<<NTOK, 256>>>(ids, emb);
    pool_partial_kernel<<<64,   256>>>(ids, emb);
    pool_final_kernel  <<<1,    256>>>();
    router_kernel      <<<1,    512>>>(wr);

    transpose_half_kernel<<<dim3(NH / 32, ND / 32, 2), dim3(32, 8)>>>(w1, ND, NH, (long)ND * NH, 0);
    transpose_half_kernel<<<dim3(ND / 32, NH / 32, 2), dim3(32, 8)>>>(w2, NH, ND, (long)NH * ND, 1);
    transpose_half_kernel<<<dim3(NV / 32, ND / 32, 1), dim3(32, 8)>>>(wh, ND, NV, 0, 2);

    mma_gemm_kernel<0><<<dim3(NH / BN, NTOK / BM, 2), 128, SMEM_2P>>>(nullptr);
    mma_gemm_kernel<1><<<dim3(ND / BN, NTOK / BM, 1), 128, SMEM_2P>>>(nullptr);
    mma_gemm_kernel<2><<<dim3(NV / BN, NTOK / BM, 1), 128, SMEM_1P>>>(out);
}

// round 13
// speedup vs baseline: 7.1751x; 1.3801x over previous
#include <cuda_runtime.h>
#include <cuda_fp16.h>
#include <stdint.h>
#include <math.h>

// ---------------- problem dims ----------------------------------------------
#define NB   4
#define NL   2048
#define ND   1024
#define NH   4096
#define NV   32000
#define NEXP 16
#define NTOK (NB*NL)     // 8192
#define KCAT (2*NH)      // 8192

#define ASCALE 1024.0f
#define INVS   (1.0f/1024.0f)

// ---------------- persistent fp16 operand storage ----------------------------
// token-side operands carry x1024 scale, single fp16 digit
__device__ __half g_Xh[NTOK * ND];
__device__ __half g_Hh[(size_t)NTOK * KCAT];
__device__ __half g_Oh[NTOK * ND];
// weight-side operands (B): single fp16, unscaled
__device__ __half g_w1f[(size_t)2 * NH * ND];
__device__ __half g_w2f[(size_t)ND * KCAT];
__device__ __half g_whf[(size_t)NV * ND];
__device__ float g_pool_part[64 * ND];
__device__ float g_pool[ND];
__device__ int   g_eidx[2];
__device__ float g_ewt[2];

// ---------------- helpers -----------------------------------------------------
__device__ __forceinline__ float gelu_tanh(float x) {
    const float u = 0.7978845608028654f * (x + 0.044715f * x * x * x);
    return 0.5f * x * (1.0f + tanhf(u));
}
__device__ __forceinline__ uint32_t pkh(__half a, __half b) {
    return (uint32_t)__half_as_ushort(a) |
           ((uint32_t)__half_as_ushort(b) << 16);
}
__device__ __forceinline__ uint32_t s2u(const void* p) {
    uint32_t a;
    asm("{ .reg .u64 t; cvta.to.shared.u64 t, %1; cvt.u32.u64 %0, t; }"
        : "=r"(a) : "l"(p));
    return a;
}

__device__ __forceinline__ void mma_f16(float* d, const uint32_t* a,
                                        const uint32_t* b) {
    asm volatile(
        "mma.sync.aligned.m16n8k16.row.col.f32.f16.f16.f32 "
        "{%0,%1,%2,%3}, {%4,%5,%6,%7}, {%8,%9}, {%0,%1,%2,%3};"
        : "+f"(d[0]), "+f"(d[1]), "+f"(d[2]), "+f"(d[3])
        : "r"(a[0]), "r"(a[1]), "r"(a[2]), "r"(a[3]),
          "r"(b[0]), "r"(b[1]));
}

#define LDSM4(r0, r1, r2, r3, addr) \
    asm volatile("ldmatrix.sync.aligned.m8n8.x4.shared.b16 {%0,%1,%2,%3}, [%4];" \
        : "=r"(r0), "=r"(r1), "=r"(r2), "=r"(r3) : "r"(addr))

#define CPASYNC16(dst, src) \
    asm volatile("cp.async.cg.shared.global [%0], [%1], 16;" \
        :: "r"(dst), "l"(src) : "memory")
#define CPCOMMIT() asm volatile("cp.async.commit_group;" ::: "memory")
#define CPWAIT2()  asm volatile("cp.async.wait_group 2;"  ::: "memory")

// chunk swizzle: 16B chunks, ci ^ bit3->bit0 (keeps ldmatrix 8-row phases conflict-free)
#define SWZ16(ci) ((uint32_t)(((ci) ^ (((ci) >> 3) & 1)) * 16))

// ---------------- embed / pool / router --------------------------------------
__global__ void gather_half_kernel(const int* __restrict__ ids,
                                   const float* __restrict__ emb)
{
    const int t = blockIdx.x;
    const int id = ids[t];
    const int c = threadIdx.x * 4;
    float4 v = *(const float4*)(emb + (size_t)id * ND + c);
    *(uint2*)(g_Xh + (size_t)t * ND + c) =
        make_uint2(pkh(__float2half_rn(v.x * ASCALE), __float2half_rn(v.y * ASCALE)),
                   pkh(__float2half_rn(v.z * ASCALE), __float2half_rn(v.w * ASCALE)));
}

__global__ void pool_partial_kernel(const int* __restrict__ ids,
                                    const float* __restrict__ emb)
{
    __shared__ int sid[128];
    const int t0 = blockIdx.x * 128;
    if (threadIdx.x < 128) sid[threadIdx.x] = ids[t0 + threadIdx.x];
    __syncthreads();
    const int c = threadIdx.x * 4;
    float4 s = make_float4(0.f, 0.f, 0.f, 0.f);
    for (int t = 0; t < 128; ++t) {
        const float4 v = *(const float4*)(emb + (size_t)sid[t] * ND + c);
        s.x += v.x; s.y += v.y; s.z += v.z; s.w += v.w;
    }
    *(float4*)(g_pool_part + blockIdx.x * ND + c) = s;
}

__global__ void pool_final_kernel()
{
    const int c = threadIdx.x * 4;
    float4 s = make_float4(0.f, 0.f, 0.f, 0.f);
    for (int b = 0; b < 64; ++b) {
        const float4 v = *(const float4*)(g_pool_part + b * ND + c);
        s.x += v.x; s.y += v.y; s.z += v.z; s.w += v.w;
    }
    const float inv = 1.0f / (float)NTOK;
    s.x *= inv; s.y *= inv; s.z *= inv; s.w *= inv;
    *(float4*)(g_pool + c) = s;
}

__global__ void router_kernel(const float* __restrict__ w_router)
{
    __shared__ float slog[NEXP];
    const int warp = threadIdx.x >> 5;
    const int lane = threadIdx.x & 31;
    float s = 0.f;
    for (int d = lane; d < ND; d += 32)
        s += g_pool[d] * w_router[d * NEXP + warp];
    #pragma unroll
    for (int o = 16; o > 0; o >>= 1) s += __shfl_down_sync(0xffffffffu, s, o);
    if (lane == 0) slog[warp] = s;
    __syncthreads();
    if (threadIdx.x == 0) {
        float v0 = -1e30f, v1 = -1e30f; int i0 = 0, i1 = 0;
        for (int n = 0; n < NEXP; ++n) {
            const float l = slog[n];
            if (l > v0) { v1 = v0; i1 = i0; v0 = l; i0 = n; }
            else if (l > v1) { v1 = l; i1 = n; }
        }
        const float e1  = expf(v1 - v0);
        const float den = 1.0f + e1;
        g_eidx[0] = i0; g_eidx[1] = i1;
        g_ewt[0] = 1.0f / den; g_ewt[1] = e1 / den;
    }
}

// ---------------- weight transpose (fp16 single) -------------------------------
__global__ void transpose_half_kernel(const float* __restrict__ src,
                                      int K, int N, long src_z, int mode)
{
    __shared__ float tile[32][33];
    const int e = blockIdx.z;
    __half* dh; long dst_z; int ld; int use_e;
    if (mode == 0)      { dh = g_w1f; dst_z = (long)NH * ND; ld = ND;   use_e = 1; }
    else if (mode == 1) { dh = g_w2f; dst_z = NH;            ld = KCAT; use_e = 1; }
    else                { dh = g_whf; dst_z = 0;             ld = ND;   use_e = 0; }

    const int sel = use_e ? g_eidx[e] : e;
    const float* in = src + (size_t)sel * src_z;
    dh += (size_t)e * dst_z;

    const int n0 = blockIdx.x * 32, k0 = blockIdx.y * 32;
    const int tx = threadIdx.x, ty = threadIdx.y;   // (32, 8)
    #pragma unroll
    for (int j = 0; j < 32; j += 8)
        tile[ty + j][tx] = in[(size_t)(k0 + ty + j) * N + n0 + tx];
    __syncthreads();
    #pragma unroll
    for (int j = 0; j < 32; j += 8)
        dh[(size_t)(n0 + ty + j) * ld + k0 + tx] =
            __float2half_rn(tile[tx][ty + j]);
}

// ---------------- fp16 single-product mma GEMM ---------------------------------
// C = A @ B^T, both operands single fp16 (A carries x1024 scale).
// 128-thread CTA, 4 warps 2x2, warp tile 64x64, 4-stage cp.async, 2 CTAs/SM.
#define BM 128
#define BN 128
#define BK 16
#define NSTAGE 4
#define OFF_BH 4096
#define STAGE  8192
#define SMEM_BYTES (NSTAGE * STAGE)   // 32768 per CTA; 2 CTAs = 64KB/SM

// MODE 0: H = gelu(X @ w1t[e]^T)*wt[e] -> Hh   (grid.z = expert)
// MODE 1: O = H @ w2t^T -> Oh
// MODE 2: LOGITS = O @ wht^T -> fp32 out
template<int MODE>
__global__ void __launch_bounds__(128, 2)
mma_gemm_kernel(float* __restrict__ Cext)
{
    constexpr int K   = (MODE == 1) ? KCAT : ND;
    constexpr int NT  = K / BK;
    constexpr int LDC = (MODE == 0) ? KCAT : ((MODE == 1) ? ND : NV);

    const __half *Ah, *Bh_;
    if (MODE == 0)      { Ah = g_Xh; Bh_ = g_w1f; }
    else if (MODE == 1) { Ah = g_Hh; Bh_ = g_w2f; }
    else                { Ah = g_Oh; Bh_ = g_whf; }

    extern __shared__ __align__(16) uint8_t smraw[];
    const uint32_t smb = s2u(smraw);

    const int tid  = threadIdx.x;
    const int w    = tid >> 5, lane = tid & 31;
    const int g    = lane >> 2, tig = lane & 3;
    const int mb   = (w >> 1) * 64;        // 2 m-warps
    const int nb   = (w & 1) * 64;         // 2 n-warps
    const int bm   = blockIdx.y * BM;
    const int bn   = blockIdx.x * BN;

    float wt = 1.f; int ccol0 = bn;
    if (MODE == 0) {
        const int e = blockIdx.z;
        wt    = g_ewt[e];
        Bh_  += (size_t)e * NH * ND;
        ccol0 = e * NH + bn;
    }

    const __half* Ab_h = Ah + (size_t)bm * K;
    const __half* Bb_h = Bh_ + (size_t)bn * K;

    // fill: 512 16B chunks / 128 threads = 4 each (2 per region)
    auto fill = [&](uint32_t sbase, int k0) {
        #pragma unroll
        for (int i = 0; i < 2; ++i) {
            const int ci = i * 128 + tid;
            const size_t go = (size_t)(ci >> 1) * K + k0 + (ci & 1) * 8;
            CPASYNC16(sbase + SWZ16(ci),          Ab_h + go);
            CPASYNC16(sbase + OFF_BH + SWZ16(ci), Bb_h + go);
        }
    };

    // ldmatrix lane offsets (verified mapping, rounds 5-11)
    const int am = lane >> 3;
    const int a_ci0 = (mb + ((am & 1) << 3) + (lane & 7)) * 2 + (am >> 1);
    const uint32_t aoff = SWZ16(a_ci0);
    const int bmm = lane >> 3;
    const int b_ci0 = (nb + ((bmm >> 1) << 3) + (lane & 7)) * 2 + (bmm & 1);
    const uint32_t boff = SWZ16(b_ci0);

    float acc[4][8][4];
    #pragma unroll
    for (int i = 0; i < 4; ++i)
        #pragma unroll
        for (int j = 0; j < 8; ++j)
            #pragma unroll
            for (int q = 0; q < 4; ++q) acc[i][j][q] = 0.f;

    // prologue: stages 0,1,2 in flight
    fill(smb, 0);                  CPCOMMIT();
    fill(smb + STAGE, BK);         CPCOMMIT();
    fill(smb + 2 * STAGE, 2 * BK); CPCOMMIT();

    int rd = 0, wr = 3;
    #pragma unroll 1
    for (int t = 0; t < NT; ++t) {
        CPWAIT2();
        __syncthreads();

        const uint32_t sb = smb + rd * STAGE;

        // B fragments for all 8 n-tiles
        uint32_t Bhf[8][2];
        #pragma unroll
        for (int p = 0; p < 4; ++p) {
            uint32_t r0, r1, r2, r3;
            LDSM4(r0, r1, r2, r3, sb + OFF_BH + boff + p * 512);
            Bhf[2*p][0] = r0; Bhf[2*p][1] = r1;
            Bhf[2*p+1][0] = r2; Bhf[2*p+1][1] = r3;
        }

        if (t + 3 < NT) fill(smb + wr * STAGE, (t + 3) * BK);
        CPCOMMIT();

        #pragma unroll
        for (int mt = 0; mt < 4; ++mt) {
            uint32_t Ahf[4];
            LDSM4(Ahf[0], Ahf[1], Ahf[2], Ahf[3], sb + aoff + mt * 512);
            #pragma unroll
            for (int nt = 0; nt < 8; ++nt)
                mma_f16(acc[mt][nt], Ahf, Bhf[nt]);
        }

        rd = (rd + 1) & 3;
        wr = (wr + 1) & 3;
    }

    // ---- epilogue (acc carries x1024 scale from A) ----
    #pragma unroll
    for (int mt = 0; mt < 4; ++mt) {
        const int row0 = bm + mb + mt * 16 + g;
        #pragma unroll
        for (int rr = 0; rr < 2; ++rr) {
            const int row = row0 + rr * 8;
            const size_t base = (size_t)row * LDC + ccol0 + nb + 2 * tig;
            #pragma unroll
            for (int nt = 0; nt < 8; ++nt) {
                float v0 = acc[mt][nt][2 * rr];
                float v1 = acc[mt][nt][2 * rr + 1];
                if (MODE == 0) {   // true value, gelu, re-apply scale
                    v0 = gelu_tanh(v0 * INVS) * wt * ASCALE;
                    v1 = gelu_tanh(v1 * INVS) * wt * ASCALE;
                }
                if (MODE == 2) {
                    *(float2*)(Cext + base + nt * 8) =
                        make_float2(v0 * INVS, v1 * INVS);
                } else {
                    __half* dh = (MODE == 0) ? g_Hh : g_Oh;
                    *(uint32_t*)(dh + base + nt * 8) =
                        pkh(__float2half_rn(v0), __float2half_rn(v1));
                }
            }
        }
    }
}

// ---------------- entry point -------------------------------------------------
extern "C" void kernel_launch(void* const* d_in, const int* in_sizes, int n_in,
                              void* d_out, int out_size)
{
    (void)in_sizes; (void)n_in; (void)out_size;
    const int*   ids = (const int*)  d_in[0];
    const float* emb = (const float*)d_in[1];
    const float* wr  = (const float*)d_in[2];
    const float* w1  = (const float*)d_in[3];
    const float* w2  = (const float*)d_in[4];
    const float* wh  = (const float*)d_in[5];
    float* out = (float*)d_out;

    cudaFuncSetAttribute(mma_gemm_kernel<0>, cudaFuncAttributeMaxDynamicSharedMemorySize, SMEM_BYTES);
    cudaFuncSetAttribute(mma_gemm_kernel<1>, cudaFuncAttributeMaxDynamicSharedMemorySize, SMEM_BYTES);
    cudaFuncSetAttribute(mma_gemm_kernel<2>, cudaFuncAttributeMaxDynamicSharedMemorySize, SMEM_BYTES);

    gather_half_kernel <<<NTOK, 256>>>(ids, emb);
    pool_partial_kernel<<<64,   256>>>(ids, emb);
    pool_final_kernel  <<<1,    256>>>();
    router_kernel      <<<1,    512>>>(wr);

    transpose_half_kernel<<<dim3(NH / 32, ND / 32, 2), dim3(32, 8)>>>(w1, ND, NH, (long)ND * NH, 0);
    transpose_half_kernel<<<dim3(ND / 32, NH / 32, 2), dim3(32, 8)>>>(w2, NH, ND, (long)NH * ND, 1);
    transpose_half_kernel<<<dim3(NV / 32, ND / 32, 1), dim3(32, 8)>>>(wh, ND, NV, 0, 2);

    mma_gemm_kernel<0><<<dim3(NH / BN, NTOK / BM, 2), 128, SMEM_BYTES>>>(nullptr);
    mma_gemm_kernel<1><<<dim3(ND / BN, NTOK / BM, 1), 128, SMEM_BYTES>>>(nullptr);
    mma_gemm_kernel<2><<<dim3(NV / BN, NTOK / BM, 1), 128, SMEM_BYTES>>>(out);
}